// round 1
// baseline (speedup 1.0000x reference)
#include <cuda_runtime.h>
#include <cuda_bf16.h>
#include <math.h>
#include <float.h>

// ---------------------------------------------------------------------------
// Problem constants
// ---------------------------------------------------------------------------
#define NTOK 2048
#define DMODEL 1024
#define HEADS 4
#define HALF 256
#define NKEYS 256
#define KNN 16
#define NEXP 16
#define DOUT 1024
// rows for stage1 topk: N*H*2
#define S1ROWS (NTOK * HEADS * 2)
// rows for stage2: N*H
#define S2ROWS (NTOK * HEADS)

// ---------------------------------------------------------------------------
// Device scratch (static: no allocation allowed)
// ---------------------------------------------------------------------------
__device__ float g_q[(size_t)NTOK * 2048];            // [N, H*2*HALF] = [2048,2048]
__device__ float g_scores[(size_t)NTOK * 2048];       // [N, H*2*NK]   = [2048,2048]
__device__ float g_v1[(size_t)S1ROWS * KNN];          // stage1 top-16 values
__device__ int   g_i1[(size_t)S1ROWS * KNN];          // stage1 top-16 indices
__device__ float g_w[(size_t)S2ROWS * KNN];           // softmax weights
__device__ int   g_idx[(size_t)S2ROWS * KNN];         // composite value indices
__device__ float g_x[(size_t)NTOK * DMODEL];          // x = data + pkm
__device__ int   g_cnt[NEXP];                         // tokens per expert
__device__ int   g_tok[NEXP * NTOK];                  // per-expert token list
__device__ float g_tokg[NEXP * NTOK];                 // per-expert gate weight

// ---------------------------------------------------------------------------
// Kernel: zero routing counters
// ---------------------------------------------------------------------------
__global__ void zero_cnt_kernel() {
    if (threadIdx.x < NEXP) g_cnt[threadIdx.x] = 0;
}

// ---------------------------------------------------------------------------
// Kernel 1: q = data @ W_q   (NN SGEMM, M=2048, N=2048, K=1024)
// 128x128x8 blocking, 8x8 per-thread micro-tile, 256 threads.
// ---------------------------------------------------------------------------
__global__ __launch_bounds__(256) void gemm_q_kernel(const float* __restrict__ A,
                                                     const float* __restrict__ B) {
    const int K = DMODEL;     // 1024
    const int N = 2048;
    __shared__ float As[8][132];
    __shared__ float Bs[8][128];
    int t = threadIdx.x;
    int m0 = blockIdx.y * 128, n0 = blockIdx.x * 128;

    float acc[8][8];
#pragma unroll
    for (int i = 0; i < 8; i++)
#pragma unroll
        for (int j = 0; j < 8; j++) acc[i][j] = 0.f;

    int ar = t >> 1, ac = (t & 1) * 4;        // A tile: 128 rows x 8 k
    int br = t >> 5, bc = (t & 31) * 4;       // B tile: 8 rows x 128 n
    int r0 = (t >> 4) * 8, c0 = (t & 15) * 8; // micro-tile origin

    const float* Aptr = A + (size_t)(m0 + ar) * K + ac;
    const float* Bptr = B + (size_t)br * N + n0 + bc;

    for (int k0 = 0; k0 < K; k0 += 8) {
        float4 av = *(const float4*)(Aptr + k0);
        float4 bv = *(const float4*)(Bptr + (size_t)k0 * N);
        As[ac + 0][ar] = av.x; As[ac + 1][ar] = av.y;
        As[ac + 2][ar] = av.z; As[ac + 3][ar] = av.w;
        *(float4*)&Bs[br][bc] = bv;
        __syncthreads();
#pragma unroll
        for (int k = 0; k < 8; k++) {
            float a[8], b[8];
#pragma unroll
            for (int i = 0; i < 8; i++) a[i] = As[k][r0 + i];
#pragma unroll
            for (int j = 0; j < 8; j++) b[j] = Bs[k][c0 + j];
#pragma unroll
            for (int i = 0; i < 8; i++)
#pragma unroll
                for (int j = 0; j < 8; j++) acc[i][j] += a[i] * b[j];
        }
        __syncthreads();
    }
#pragma unroll
    for (int i = 0; i < 8; i++) {
        float* Cp = g_q + (size_t)(m0 + r0 + i) * N + n0 + c0;
        *(float4*)(Cp)     = make_float4(acc[i][0], acc[i][1], acc[i][2], acc[i][3]);
        *(float4*)(Cp + 4) = make_float4(acc[i][4], acc[i][5], acc[i][6], acc[i][7]);
    }
}

// ---------------------------------------------------------------------------
// Kernel 2: scores[n][hc][k] = sum_d q[n][hc*256+d] * keys[hc][k][d]
// Batched NT SGEMM: per hc (grid.z = 8): M=2048, N(keys)=256, K=256.
// ---------------------------------------------------------------------------
__global__ __launch_bounds__(256) void gemm_scores_kernel(const float* __restrict__ keys) {
    int hc = blockIdx.z;
    const float* A = g_q + hc * HALF;                       // lda 2048
    const float* B = keys + (size_t)hc * NKEYS * HALF;      // [256 keys][256 d]
    float* C = g_scores + hc * NKEYS;                       // ldc 2048

    __shared__ float As[8][132];
    __shared__ float Bs[8][132];
    int t = threadIdx.x;
    int m0 = blockIdx.y * 128, n0 = blockIdx.x * 128;

    float acc[8][8];
#pragma unroll
    for (int i = 0; i < 8; i++)
#pragma unroll
        for (int j = 0; j < 8; j++) acc[i][j] = 0.f;

    int ar = t >> 1, ac = (t & 1) * 4;
    int r0 = (t >> 4) * 8, c0 = (t & 15) * 8;

    const float* Aptr = A + (size_t)(m0 + ar) * 2048 + ac;
    const float* Bptr = B + (size_t)(n0 + ar) * HALF + ac;  // key row = ar (transposed tile)

    for (int k0 = 0; k0 < HALF; k0 += 8) {
        float4 av = *(const float4*)(Aptr + k0);
        float4 bv = *(const float4*)(Bptr + k0);
        As[ac + 0][ar] = av.x; As[ac + 1][ar] = av.y;
        As[ac + 2][ar] = av.z; As[ac + 3][ar] = av.w;
        Bs[ac + 0][ar] = bv.x; Bs[ac + 1][ar] = bv.y;
        Bs[ac + 2][ar] = bv.z; Bs[ac + 3][ar] = bv.w;
        __syncthreads();
#pragma unroll
        for (int k = 0; k < 8; k++) {
            float a[8], b[8];
#pragma unroll
            for (int i = 0; i < 8; i++) a[i] = As[k][r0 + i];
#pragma unroll
            for (int j = 0; j < 8; j++) b[j] = Bs[k][c0 + j];
#pragma unroll
            for (int i = 0; i < 8; i++)
#pragma unroll
                for (int j = 0; j < 8; j++) acc[i][j] += a[i] * b[j];
        }
        __syncthreads();
    }
#pragma unroll
    for (int i = 0; i < 8; i++) {
        float* Cp = C + (size_t)(m0 + r0 + i) * 2048 + n0 + c0;
        *(float4*)(Cp)     = make_float4(acc[i][0], acc[i][1], acc[i][2], acc[i][3]);
        *(float4*)(Cp + 4) = make_float4(acc[i][4], acc[i][5], acc[i][6], acc[i][7]);
    }
}

// ---------------------------------------------------------------------------
// Kernel 3: stage-1 top-16 of 256 scores per (n,h,c) row. One warp per row.
// Element t of the row is held by lane t%32, slot t/32 (coalesced loads).
// Deterministic tie-break: lowest index wins (matches jax top_k ordering).
// ---------------------------------------------------------------------------
__global__ __launch_bounds__(256) void topk1_kernel() {
    int row  = (blockIdx.x * blockDim.x + threadIdx.x) >> 5; // 0..16383
    int lane = threadIdx.x & 31;
    const float* src = g_scores + (size_t)row * NKEYS;

    float lv[8];
#pragma unroll
    for (int r = 0; r < 8; r++) lv[r] = src[r * 32 + lane];

    float* vo = g_v1 + (size_t)row * KNN;
    int*   io = g_i1 + (size_t)row * KNN;

    for (int sel = 0; sel < KNN; sel++) {
        float bv = lv[0]; int bg = lane;
#pragma unroll
        for (int r = 1; r < 8; r++) {
            int gidx = r * 32 + lane;
            if (lv[r] > bv) { bv = lv[r]; bg = gidx; }
        }
#pragma unroll
        for (int off = 16; off; off >>= 1) {
            float ov = __shfl_xor_sync(0xffffffffu, bv, off);
            int   og = __shfl_xor_sync(0xffffffffu, bg, off);
            if (ov > bv || (ov == bv && og < bg)) { bv = ov; bg = og; }
        }
        if (lane == 0) { vo[sel] = bv; io[sel] = bg; }
        if ((bg & 31) == lane) lv[bg >> 5] = -FLT_MAX;
    }
}

// ---------------------------------------------------------------------------
// Kernel 4: stage-2 — cartesian 16x16 candidates, top-16, softmax.
// One warp per (n,h). 8 warps/block.
// ---------------------------------------------------------------------------
__global__ __launch_bounds__(256) void topk2_kernel() {
    int row  = (blockIdx.x * blockDim.x + threadIdx.x) >> 5; // 0..8191 = n*H + h
    int lane = threadIdx.x & 31;
    int wp   = threadIdx.x >> 5;

    __shared__ float sv1[8][16], sv2[8][16];
    __shared__ int   si1[8][16], si2[8][16];
    __shared__ float selv[8][16];
    __shared__ int   seli[8][16];

    int r1 = row * 2, r2 = row * 2 + 1;
    if (lane < 16) {
        sv1[wp][lane] = g_v1[(size_t)r1 * KNN + lane];
        si1[wp][lane] = g_i1[(size_t)r1 * KNN + lane];
    } else {
        sv2[wp][lane - 16] = g_v1[(size_t)r2 * KNN + (lane - 16)];
        si2[wp][lane - 16] = g_i1[(size_t)r2 * KNN + (lane - 16)];
    }
    __syncwarp();

    float lv[8];
#pragma unroll
    for (int r = 0; r < 8; r++) {
        int tcand = r * 32 + lane;
        lv[r] = sv1[wp][tcand >> 4] + sv2[wp][tcand & 15];
    }

    for (int sel = 0; sel < KNN; sel++) {
        float bv = lv[0]; int bg = lane;
#pragma unroll
        for (int r = 1; r < 8; r++) {
            int gidx = r * 32 + lane;
            if (lv[r] > bv) { bv = lv[r]; bg = gidx; }
        }
#pragma unroll
        for (int off = 16; off; off >>= 1) {
            float ov = __shfl_xor_sync(0xffffffffu, bv, off);
            int   og = __shfl_xor_sync(0xffffffffu, bg, off);
            if (ov > bv || (ov == bv && og < bg)) { bv = ov; bg = og; }
        }
        if (lane == 0) {
            selv[wp][sel] = bv;
            seli[wp][sel] = si1[wp][bg >> 4] * NKEYS + si2[wp][bg & 15];
        }
        if ((bg & 31) == lane) lv[bg >> 5] = -FLT_MAX;
    }
    __syncwarp();

    // softmax over the 16 selected (selv[0] is the max — selected first)
    float mx = selv[wp][0];
    float e = (lane < 16) ? expf(selv[wp][lane] - mx) : 0.f;
    float s = e;
#pragma unroll
    for (int off = 16; off; off >>= 1) s += __shfl_xor_sync(0xffffffffu, s, off);
    if (lane < 16) {
        g_w[(size_t)row * KNN + lane]   = e / s;
        g_idx[(size_t)row * KNN + lane] = seli[wp][lane];
    }
}

// ---------------------------------------------------------------------------
// Kernel 5: x[n] = data[n] + sum_{h,k} w[n,h,k] * values[idx[n,h,k]]
// One block per token; 256 threads x float4 covers D=1024. 512 MB coalesced.
// ---------------------------------------------------------------------------
__global__ __launch_bounds__(256) void gather_kernel(const float* __restrict__ data,
                                                     const float* __restrict__ values) {
    int n = blockIdx.x;
    int t = threadIdx.x;
    __shared__ float sw[HEADS * KNN];
    __shared__ int   sidx[HEADS * KNN];
    if (t < HEADS * KNN) {
        sw[t]   = g_w[(size_t)n * HEADS * KNN + t];
        sidx[t] = g_idx[(size_t)n * HEADS * KNN + t];
    }
    __syncthreads();

    float4 acc = *(const float4*)(data + (size_t)n * DMODEL + t * 4);
#pragma unroll 4
    for (int j = 0; j < HEADS * KNN; j++) {
        const float4 v = *(const float4*)(values + (size_t)sidx[j] * DMODEL + t * 4);
        float wj = sw[j];
        acc.x += wj * v.x; acc.y += wj * v.y;
        acc.z += wj * v.z; acc.w += wj * v.w;
    }
    *(float4*)(g_x + (size_t)n * DMODEL + t * 4) = acc;
}

// ---------------------------------------------------------------------------
// Kernel 6: gate logits + top-2 + softmax + routing-list build.
// One block (128 threads) per token.
// ---------------------------------------------------------------------------
__global__ __launch_bounds__(128) void gate_route_kernel(const float* __restrict__ gW,
                                                         const float* __restrict__ gb) {
    int n = blockIdx.x;
    int t = threadIdx.x;          // 128
    int e = t & 15, seg = t >> 4; // 8 segments of 128 d each

    const float* xr = g_x + (size_t)n * DMODEL;
    float p = 0.f;
    int dbeg = seg * 128;
    for (int d = dbeg; d < dbeg + 128; d++) p += xr[d] * gW[d * NEXP + e];

    __shared__ float sacc[128];
    __shared__ float lg[NEXP];
    sacc[t] = p;
    __syncthreads();
    if (t < NEXP) {
        float s = 0.f;
        for (int sgi = 0; sgi < 8; sgi++) s += sacc[sgi * 16 + t];
        lg[t] = s + gb[t];
    }
    __syncthreads();
    if (t == 0) {
        int b0 = 0; float v0 = lg[0];
        for (int i = 1; i < NEXP; i++) if (lg[i] > v0) { v0 = lg[i]; b0 = i; }
        int b1 = -1; float v1 = -FLT_MAX;
        for (int i = 0; i < NEXP; i++) {
            if (i == b0) continue;
            if (lg[i] > v1) { v1 = lg[i]; b1 = i; }
        }
        float gate0 = 1.f / (1.f + expf(v1 - v0));  // softmax over [v0, v1]
        float gate1 = 1.f - gate0;
        int p0 = atomicAdd(&g_cnt[b0], 1);
        g_tok[b0 * NTOK + p0] = n;  g_tokg[b0 * NTOK + p0] = gate0;
        int p1 = atomicAdd(&g_cnt[b1], 1);
        g_tok[b1 * NTOK + p1] = n;  g_tokg[b1 * NTOK + p1] = gate1;
    }
}

// ---------------------------------------------------------------------------
// Kernel 7: grouped expert GEMM with gathered rows.
// grid (DOUT/128, maxMtiles=16, NEXP). Blocks past cnt[e] exit immediately.
// Epilogue: out[tok] += g * (acc + bias)  via atomicAdd (each token hit by
// exactly 2 experts; out is zeroed beforehand).
// ---------------------------------------------------------------------------
__global__ __launch_bounds__(256) void expert_gemm_kernel(const float* __restrict__ eW,
                                                          const float* __restrict__ eB,
                                                          float* __restrict__ out) {
    int ex  = blockIdx.z;
    int cnt = g_cnt[ex];
    int m0  = blockIdx.y * 128;
    if (m0 >= cnt) return;
    int n0 = blockIdx.x * 128;

    const float* B = eW + (size_t)ex * DMODEL * DOUT;

    __shared__ float As[8][132];
    __shared__ float Bs[8][128];
    __shared__ int   stok[128];
    __shared__ float sg[128];

    int t = threadIdx.x;
    if (t < 128) {
        int i = m0 + t;
        bool v = i < cnt;
        stok[t] = v ? g_tok[ex * NTOK + i] : -1;
        sg[t]   = v ? g_tokg[ex * NTOK + i] : 0.f;
    }
    __syncthreads();

    float acc[8][8];
#pragma unroll
    for (int i = 0; i < 8; i++)
#pragma unroll
        for (int j = 0; j < 8; j++) acc[i][j] = 0.f;

    int ar = t >> 1, ac = (t & 1) * 4;
    int br = t >> 5, bc = (t & 31) * 4;
    int r0 = (t >> 4) * 8, c0 = (t & 15) * 8;

    int tokA = stok[ar];
    const float* Aptr = (tokA >= 0) ? (g_x + (size_t)tokA * DMODEL + ac) : g_x;
    const float* Bptr = B + (size_t)br * DOUT + n0 + bc;

    for (int k0 = 0; k0 < DMODEL; k0 += 8) {
        float4 av = (tokA >= 0) ? *(const float4*)(Aptr + k0)
                                : make_float4(0.f, 0.f, 0.f, 0.f);
        float4 bv = *(const float4*)(Bptr + (size_t)k0 * DOUT);
        As[ac + 0][ar] = av.x; As[ac + 1][ar] = av.y;
        As[ac + 2][ar] = av.z; As[ac + 3][ar] = av.w;
        *(float4*)&Bs[br][bc] = bv;
        __syncthreads();
#pragma unroll
        for (int k = 0; k < 8; k++) {
            float a[8], b[8];
#pragma unroll
            for (int i = 0; i < 8; i++) a[i] = As[k][r0 + i];
#pragma unroll
            for (int j = 0; j < 8; j++) b[j] = Bs[k][c0 + j];
#pragma unroll
            for (int i = 0; i < 8; i++)
#pragma unroll
                for (int j = 0; j < 8; j++) acc[i][j] += a[i] * b[j];
        }
        __syncthreads();
    }

    const float* bias = eB + (size_t)ex * DOUT + n0 + c0;
#pragma unroll
    for (int i = 0; i < 8; i++) {
        int tok = stok[r0 + i];
        if (tok < 0) continue;
        float g = sg[r0 + i];
        float* op = out + (size_t)tok * DOUT + n0 + c0;
#pragma unroll
        for (int j = 0; j < 8; j++)
            atomicAdd(op + j, g * (acc[i][j] + bias[j]));
    }
}

// ---------------------------------------------------------------------------
// Launch
// ---------------------------------------------------------------------------
extern "C" void kernel_launch(void* const* d_in, const int* in_sizes, int n_in,
                              void* d_out, int out_size) {
    const float* data     = (const float*)d_in[0];
    const float* W_q      = (const float*)d_in[1];
    const float* keys     = (const float*)d_in[2];
    const float* values   = (const float*)d_in[3];
    const float* gate_W   = (const float*)d_in[4];
    const float* gate_b   = (const float*)d_in[5];
    const float* expert_W = (const float*)d_in[6];
    const float* expert_b = (const float*)d_in[7];
    float* out = (float*)d_out;

    (void)in_sizes; (void)n_in;

    // out is poisoned to 0xAA; expert GEMM accumulates, so zero it.
    cudaMemsetAsync(out, 0, (size_t)out_size * sizeof(float));
    zero_cnt_kernel<<<1, 32>>>();

    // 1. q = data @ W_q
    gemm_q_kernel<<<dim3(16, 16), 256>>>(data, W_q);
    // 2. batched scores (8 sub-GEMMs via grid.z)
    gemm_scores_kernel<<<dim3(2, 16, 8), 256>>>(keys);
    // 3. stage-1 top-16 per (n,h,c)
    topk1_kernel<<<S1ROWS / 8, 256>>>();
    // 4. stage-2 cartesian top-16 + softmax per (n,h)
    topk2_kernel<<<S2ROWS / 8, 256>>>();
    // 5. value gather + residual  -> x
    gather_kernel<<<NTOK, 256>>>(data, values);
    // 6. gating + top-2 routing list build
    gate_route_kernel<<<NTOK, 128>>>(gate_W, gate_b);
    // 7. grouped expert GEMM -> out
    expert_gemm_kernel<<<dim3(DOUT / 128, NTOK / 128, NEXP), 256>>>(expert_W, expert_b, out);
}

// round 3
// speedup vs baseline: 1.7954x; 1.7954x over previous
#include <cuda_runtime.h>
#include <cuda_bf16.h>
#include <math.h>
#include <float.h>
#include <stdint.h>

// ---------------------------------------------------------------------------
// Problem constants
// ---------------------------------------------------------------------------
#define NTOK 2048
#define DMODEL 1024
#define HEADS 4
#define HALF 256
#define NKEYS 256
#define KNN 16
#define NEXP 16
#define DOUT 1024
#define S1ROWS (NTOK * HEADS * 2)
#define S2ROWS (NTOK * HEADS)

// ---------------------------------------------------------------------------
// GEMM tiling: 128x128 CTA tile, K-chunk 64 (bf16, 128B rows, SW128 swizzle)
// 8 warps: 2 (M) x 4 (N); warp tile 64x32; mma.sync m16n8k16 bf16.
// 3-term split: C = Ahi*Bhi + Alo*Bhi + Ahi*Blo  (fp32-accurate)
// ---------------------------------------------------------------------------
#define BM 128
#define BN 128
#define KT 64

#define SM_TOK   64
#define SM_G     576
#define SM_TILES 2048
#define TILE_A_HI 0
#define TILE_A_LO 16384
#define TILE_B_HI 32768
#define TILE_B_LO 49152
#define STAGE_BYTES 65536
#define SMEM_TOTAL_GEMM (SM_TILES + STAGE_BYTES)   // 67584 bytes

#define SW128(x) ((x) ^ (((x) >> 3) & 0x70))

// ---------------------------------------------------------------------------
// PTX wrappers (baseline sm_80+ instructions only)
// ---------------------------------------------------------------------------
static __device__ __forceinline__ void ldsm4(uint32_t* r, uint32_t sa) {
    asm volatile("ldmatrix.sync.aligned.m8n8.x4.shared.b16 {%0,%1,%2,%3}, [%4];"
                 : "=r"(r[0]), "=r"(r[1]), "=r"(r[2]), "=r"(r[3]) : "r"(sa));
}

static __device__ __forceinline__ void mma16816(float* c, const uint32_t* a,
                                                uint32_t b0, uint32_t b1) {
    asm volatile("mma.sync.aligned.m16n8k16.row.col.f32.bf16.bf16.f32 "
                 "{%0,%1,%2,%3}, {%4,%5,%6,%7}, {%8,%9}, {%0,%1,%2,%3};"
                 : "+f"(c[0]), "+f"(c[1]), "+f"(c[2]), "+f"(c[3])
                 : "r"(a[0]), "r"(a[1]), "r"(a[2]), "r"(a[3]), "r"(b0), "r"(b1));
}

// ---------------------------------------------------------------------------
// Device scratch
// ---------------------------------------------------------------------------
__device__ float g_q[(size_t)NTOK * 2048];
__device__ float g_scores[(size_t)NTOK * 2048];
__device__ float g_v1[(size_t)S1ROWS * KNN];
__device__ int   g_i1[(size_t)S1ROWS * KNN];
__device__ float g_w[(size_t)S2ROWS * KNN];
__device__ int   g_idx[(size_t)S2ROWS * KNN];
__device__ float g_x[(size_t)NTOK * DMODEL];
__device__ int   g_cnt[NEXP];
__device__ int   g_tok[NEXP * NTOK];
__device__ float g_tokg[NEXP * NTOK];

__global__ void zero_cnt_kernel() {
    if (threadIdx.x < NEXP) g_cnt[threadIdx.x] = 0;
}

// ---------------------------------------------------------------------------
// fp32 -> bf16 hi/lo split, 4 consecutive k-elements, swizzled 8B stores
// ---------------------------------------------------------------------------
static __device__ __forceinline__ void split_store4(char* hi_base, char* lo_base,
                                                    int byteoff, float4 v) {
    __nv_bfloat16 h0 = __float2bfloat16(v.x), h1 = __float2bfloat16(v.y),
                  h2 = __float2bfloat16(v.z), h3 = __float2bfloat16(v.w);
    __nv_bfloat16 l0 = __float2bfloat16(v.x - __bfloat162float(h0));
    __nv_bfloat16 l1 = __float2bfloat16(v.y - __bfloat162float(h1));
    __nv_bfloat16 l2 = __float2bfloat16(v.z - __bfloat162float(h2));
    __nv_bfloat16 l3 = __float2bfloat16(v.w - __bfloat162float(h3));
    uint2 hv, lv;
    hv.x = (uint32_t)__bfloat16_as_ushort(h0) | ((uint32_t)__bfloat16_as_ushort(h1) << 16);
    hv.y = (uint32_t)__bfloat16_as_ushort(h2) | ((uint32_t)__bfloat16_as_ushort(h3) << 16);
    lv.x = (uint32_t)__bfloat16_as_ushort(l0) | ((uint32_t)__bfloat16_as_ushort(l1) << 16);
    lv.y = (uint32_t)__bfloat16_as_ushort(l2) | ((uint32_t)__bfloat16_as_ushort(l3) << 16);
    int sw = SW128(byteoff);
    *(uint2*)(hi_base + sw) = hv;
    *(uint2*)(lo_base + sw) = lv;
}

// K-major source tile: src[128 rows][lda], take cols [0,64)
static __device__ __forceinline__ void load_tile_direct(char* hi, char* lo,
                                                        const float* src, int lda, int t) {
    int k4 = t & 15;
    int rbase = t >> 4;
#pragma unroll
    for (int p = 0; p < 8; p++) {
        int r = p * 16 + rbase;
        float4 v = *(const float4*)(src + (size_t)r * lda + k4 * 4);
        split_store4(hi, lo, r * 128 + k4 * 8, v);
    }
}

// Transposed source: src[K rows][ldb cols]; produce [n][k] tile (n rows of 64 k)
static __device__ __forceinline__ void load_tile_transposed(char* hi, char* lo,
                                                            const float* src, int ldb, int t) {
    int n = t >> 1;
    int kh = (t & 1) * 32;
    const float* p = src + n + (size_t)kh * ldb;
#pragma unroll
    for (int kk = 0; kk < 32; kk += 4) {
        float a0 = p[(size_t)(kk + 0) * ldb];
        float a1 = p[(size_t)(kk + 1) * ldb];
        float a2 = p[(size_t)(kk + 2) * ldb];
        float a3 = p[(size_t)(kk + 3) * ldb];
        split_store4(hi, lo, n * 128 + (kh + kk) * 2, make_float4(a0, a1, a2, a3));
    }
}

// ---------------------------------------------------------------------------
// Warp-level compute over one 64-k smem stage (3-pass split), accumulating
// into acc[mt][nt][4].
// ---------------------------------------------------------------------------
static __device__ __forceinline__ void compute_stage(uint32_t stage_sa, int wm, int wn,
                                                     int lane, float acc[4][4][4]) {
    uint32_t aHI = stage_sa + TILE_A_HI, aLO = stage_sa + TILE_A_LO;
    uint32_t bHI = stage_sa + TILE_B_HI, bLO = stage_sa + TILE_B_LO;
    int lrow = lane & 15;
    int lcol = (lane >> 4) * 16;   // byte offset for second 8-col block

#pragma unroll
    for (int ks = 0; ks < 4; ks++) {
        int kb = ks * 32;          // k16 step = 32 bytes
        uint32_t bh[2][4], bl[2][4];
#pragma unroll
        for (int np = 0; np < 2; np++) {
            int boff = SW128((wn * 32 + np * 16 + lrow) * 128 + kb + lcol);
            ldsm4(bh[np], bHI + boff);
            ldsm4(bl[np], bLO + boff);
        }
#pragma unroll
        for (int mt = 0; mt < 4; mt++) {
            uint32_t ah[4], al[4];
            int aoff = SW128((wm * 64 + mt * 16 + lrow) * 128 + kb + lcol);
            ldsm4(ah, aHI + aoff);
            ldsm4(al, aLO + aoff);
#pragma unroll
            for (int nt = 0; nt < 4; nt++) {
                int np = nt >> 1, h = nt & 1;
                mma16816(acc[mt][nt], ah, bh[np][h], bh[np][h + 2]);
                mma16816(acc[mt][nt], al, bh[np][h], bh[np][h + 2]);
                mma16816(acc[mt][nt], ah, bl[np][h], bl[np][h + 2]);
            }
        }
    }
}

// ---------------------------------------------------------------------------
// Kernel 1: q = data @ W_q   M=2048 N=2048 K=1024. grid(16,16).
// ---------------------------------------------------------------------------
__global__ __launch_bounds__(256, 2) void mm_q_kernel(const float* __restrict__ A,
                                                      const float* __restrict__ Bsrc) {
    extern __shared__ char smem[];
    uint32_t sb;
    asm("{ .reg .u64 t; cvta.to.shared.u64 t, %1; cvt.u32.u64 %0, t; }" : "=r"(sb) : "l"(smem));
    int t = threadIdx.x, wid = t >> 5, lane = t & 31;
    int wm = wid & 1, wn = wid >> 1;
    int m0 = blockIdx.y * BM, n0 = blockIdx.x * BN;
    char* cst = smem + SM_TILES;
    uint32_t stage_sa = sb + SM_TILES;

    float acc[4][4][4];
#pragma unroll
    for (int i = 0; i < 4; i++)
#pragma unroll
        for (int j = 0; j < 4; j++)
#pragma unroll
            for (int k = 0; k < 4; k++) acc[i][j][k] = 0.f;

    for (int kt = 0; kt < DMODEL / KT; kt++) {
        load_tile_direct(cst + TILE_A_HI, cst + TILE_A_LO,
                         A + (size_t)m0 * DMODEL + kt * KT, DMODEL, t);
        load_tile_transposed(cst + TILE_B_HI, cst + TILE_B_LO,
                             Bsrc + (size_t)(kt * KT) * 2048 + n0, 2048, t);
        __syncthreads();
        compute_stage(stage_sa, wm, wn, lane, acc);
        __syncthreads();
    }

#pragma unroll
    for (int mt = 0; mt < 4; mt++)
#pragma unroll
        for (int nt = 0; nt < 4; nt++) {
            int r = m0 + wm * 64 + mt * 16 + (lane >> 2);
            int c = n0 + wn * 32 + nt * 8 + (lane & 3) * 2;
            *(float2*)(g_q + (size_t)r * 2048 + c) =
                make_float2(acc[mt][nt][0], acc[mt][nt][1]);
            *(float2*)(g_q + (size_t)(r + 8) * 2048 + c) =
                make_float2(acc[mt][nt][2], acc[mt][nt][3]);
        }
}

// ---------------------------------------------------------------------------
// Kernel 2: scores. grid(2,16,8): x=key tile, y=token tile, z=hc.
// ---------------------------------------------------------------------------
__global__ __launch_bounds__(256, 2) void mm_scores_kernel(const float* __restrict__ keys) {
    extern __shared__ char smem[];
    uint32_t sb;
    asm("{ .reg .u64 t; cvta.to.shared.u64 t, %1; cvt.u32.u64 %0, t; }" : "=r"(sb) : "l"(smem));
    int t = threadIdx.x, wid = t >> 5, lane = t & 31;
    int wm = wid & 1, wn = wid >> 1;
    int hc = blockIdx.z;
    int m0 = blockIdx.y * BM, n0 = blockIdx.x * BN;
    const float* A = g_q + hc * HALF;                   // lda 2048
    const float* B = keys + (size_t)hc * NKEYS * HALF;  // K-major [key][d]
    char* cst = smem + SM_TILES;
    uint32_t stage_sa = sb + SM_TILES;

    float acc[4][4][4];
#pragma unroll
    for (int i = 0; i < 4; i++)
#pragma unroll
        for (int j = 0; j < 4; j++)
#pragma unroll
            for (int k = 0; k < 4; k++) acc[i][j][k] = 0.f;

    for (int kt = 0; kt < HALF / KT; kt++) {
        load_tile_direct(cst + TILE_A_HI, cst + TILE_A_LO,
                         A + (size_t)m0 * 2048 + kt * KT, 2048, t);
        load_tile_direct(cst + TILE_B_HI, cst + TILE_B_LO,
                         B + (size_t)n0 * HALF + kt * KT, HALF, t);
        __syncthreads();
        compute_stage(stage_sa, wm, wn, lane, acc);
        __syncthreads();
    }

#pragma unroll
    for (int mt = 0; mt < 4; mt++)
#pragma unroll
        for (int nt = 0; nt < 4; nt++) {
            int r = m0 + wm * 64 + mt * 16 + (lane >> 2);
            int c = hc * NKEYS + n0 + wn * 32 + nt * 8 + (lane & 3) * 2;
            *(float2*)(g_scores + (size_t)r * 2048 + c) =
                make_float2(acc[mt][nt][0], acc[mt][nt][1]);
            *(float2*)(g_scores + (size_t)(r + 8) * 2048 + c) =
                make_float2(acc[mt][nt][2], acc[mt][nt][3]);
        }
}

// ---------------------------------------------------------------------------
// Kernel 3: stage-1 top-16 of 256 per row (lane-local cached max). 1 warp/row.
// ---------------------------------------------------------------------------
__global__ __launch_bounds__(256) void topk1_kernel() {
    int row  = (blockIdx.x * blockDim.x + threadIdx.x) >> 5;
    int lane = threadIdx.x & 31;
    const float* src = g_scores + (size_t)row * NKEYS;

    float lv[8];
#pragma unroll
    for (int r = 0; r < 8; r++) lv[r] = src[r * 32 + lane];

    float lmax = lv[0]; int lslot = 0;
#pragma unroll
    for (int r = 1; r < 8; r++) if (lv[r] > lmax) { lmax = lv[r]; lslot = r; }

    float* vo = g_v1 + (size_t)row * KNN;
    int*   io = g_i1 + (size_t)row * KNN;

    for (int sel = 0; sel < KNN; sel++) {
        float bv = lmax; int bg = lslot * 32 + lane;
#pragma unroll
        for (int off = 16; off; off >>= 1) {
            float ov = __shfl_xor_sync(0xffffffffu, bv, off);
            int   og = __shfl_xor_sync(0xffffffffu, bg, off);
            if (ov > bv || (ov == bv && og < bg)) { bv = ov; bg = og; }
        }
        if (lane == 0) { vo[sel] = bv; io[sel] = bg; }
        if ((bg & 31) == lane) {
            lv[bg >> 5] = -FLT_MAX;
            lmax = lv[0]; lslot = 0;
#pragma unroll
            for (int r = 1; r < 8; r++) if (lv[r] > lmax) { lmax = lv[r]; lslot = r; }
        }
    }
}

// ---------------------------------------------------------------------------
// Kernel 4: stage-2 cartesian top-16 + softmax. One warp per (n,h).
// ---------------------------------------------------------------------------
__global__ __launch_bounds__(256) void topk2_kernel() {
    int row  = (blockIdx.x * blockDim.x + threadIdx.x) >> 5;
    int lane = threadIdx.x & 31;
    int wp   = threadIdx.x >> 5;

    __shared__ float sv1[8][16], sv2[8][16];
    __shared__ int   si1[8][16], si2[8][16];
    __shared__ float selv[8][16];
    __shared__ int   seli[8][16];

    int r1 = row * 2, r2 = row * 2 + 1;
    if (lane < 16) {
        sv1[wp][lane] = g_v1[(size_t)r1 * KNN + lane];
        si1[wp][lane] = g_i1[(size_t)r1 * KNN + lane];
    } else {
        sv2[wp][lane - 16] = g_v1[(size_t)r2 * KNN + (lane - 16)];
        si2[wp][lane - 16] = g_i1[(size_t)r2 * KNN + (lane - 16)];
    }
    __syncwarp();

    float lv[8];
#pragma unroll
    for (int r = 0; r < 8; r++) {
        int c = r * 32 + lane;
        lv[r] = sv1[wp][c >> 4] + sv2[wp][c & 15];
    }
    float lmax = lv[0]; int lslot = 0;
#pragma unroll
    for (int r = 1; r < 8; r++) if (lv[r] > lmax) { lmax = lv[r]; lslot = r; }

    for (int sel = 0; sel < KNN; sel++) {
        float bv = lmax; int bg = lslot * 32 + lane;
#pragma unroll
        for (int off = 16; off; off >>= 1) {
            float ov = __shfl_xor_sync(0xffffffffu, bv, off);
            int   og = __shfl_xor_sync(0xffffffffu, bg, off);
            if (ov > bv || (ov == bv && og < bg)) { bv = ov; bg = og; }
        }
        if (lane == 0) {
            selv[wp][sel] = bv;
            seli[wp][sel] = si1[wp][bg >> 4] * NKEYS + si2[wp][bg & 15];
        }
        if ((bg & 31) == lane) {
            lv[bg >> 5] = -FLT_MAX;
            lmax = lv[0]; lslot = 0;
#pragma unroll
            for (int r = 1; r < 8; r++) if (lv[r] > lmax) { lmax = lv[r]; lslot = r; }
        }
    }
    __syncwarp();

    float mx = selv[wp][0];
    float e = (lane < 16) ? expf(selv[wp][lane] - mx) : 0.f;
    float s = e;
#pragma unroll
    for (int off = 16; off; off >>= 1) s += __shfl_xor_sync(0xffffffffu, s, off);
    if (lane < 16) {
        g_w[(size_t)row * KNN + lane]   = e / s;
        g_idx[(size_t)row * KNN + lane] = seli[wp][lane];
    }
}

// ---------------------------------------------------------------------------
// Kernel 5: value gather + residual -> g_x. One block per token.
// ---------------------------------------------------------------------------
__global__ __launch_bounds__(256) void gather_kernel(const float* __restrict__ data,
                                                     const float* __restrict__ values) {
    int n = blockIdx.x;
    int t = threadIdx.x;
    __shared__ float sw[HEADS * KNN];
    __shared__ int   sidx[HEADS * KNN];
    if (t < HEADS * KNN) {
        sw[t]   = g_w[(size_t)n * HEADS * KNN + t];
        sidx[t] = g_idx[(size_t)n * HEADS * KNN + t];
    }
    __syncthreads();

    float4 acc = *(const float4*)(data + (size_t)n * DMODEL + t * 4);
#pragma unroll 4
    for (int j = 0; j < HEADS * KNN; j++) {
        const float4 v = *(const float4*)(values + (size_t)sidx[j] * DMODEL + t * 4);
        float wj = sw[j];
        acc.x += wj * v.x; acc.y += wj * v.y;
        acc.z += wj * v.z; acc.w += wj * v.w;
    }
    *(float4*)(g_x + (size_t)n * DMODEL + t * 4) = acc;
}

// ---------------------------------------------------------------------------
// Kernel 6: gating + top-2 routing. One block (128 thr) per token.
// ---------------------------------------------------------------------------
__global__ __launch_bounds__(128) void gate_route_kernel(const float* __restrict__ gW,
                                                         const float* __restrict__ gb) {
    int n = blockIdx.x;
    int t = threadIdx.x;
    int e = t & 15, seg = t >> 4;

    const float* xr = g_x + (size_t)n * DMODEL;
    float p = 0.f;
    int dbeg = seg * 128;
    for (int d = dbeg; d < dbeg + 128; d++) p += xr[d] * gW[d * NEXP + e];

    __shared__ float sacc[128];
    __shared__ float lg[NEXP];
    sacc[t] = p;
    __syncthreads();
    if (t < NEXP) {
        float s = 0.f;
        for (int sgi = 0; sgi < 8; sgi++) s += sacc[sgi * 16 + t];
        lg[t] = s + gb[t];
    }
    __syncthreads();
    if (t == 0) {
        int b0 = 0; float v0 = lg[0];
        for (int i = 1; i < NEXP; i++) if (lg[i] > v0) { v0 = lg[i]; b0 = i; }
        int b1 = -1; float v1 = -FLT_MAX;
        for (int i = 0; i < NEXP; i++) {
            if (i == b0) continue;
            if (lg[i] > v1) { v1 = lg[i]; b1 = i; }
        }
        float gate0 = 1.f / (1.f + expf(v1 - v0));
        float gate1 = 1.f - gate0;
        int p0 = atomicAdd(&g_cnt[b0], 1);
        g_tok[b0 * NTOK + p0] = n;  g_tokg[b0 * NTOK + p0] = gate0;
        int p1 = atomicAdd(&g_cnt[b1], 1);
        g_tok[b1 * NTOK + p1] = n;  g_tokg[b1 * NTOK + p1] = gate1;
    }
}

// ---------------------------------------------------------------------------
// Kernel 7: grouped expert GEMM. grid(8, 16, NEXP), early exit past cnt.
// Epilogue: out[tok] += g * (acc + bias) via atomicAdd.
// ---------------------------------------------------------------------------
__global__ __launch_bounds__(256, 2) void mm_expert_kernel(const float* __restrict__ eW,
                                                           const float* __restrict__ eB,
                                                           float* __restrict__ out) {
    int ex  = blockIdx.z;
    int cnt = g_cnt[ex];
    int m0  = blockIdx.y * BM;
    if (m0 >= cnt) return;
    int n0 = blockIdx.x * BN;

    extern __shared__ char smem[];
    uint32_t sb;
    asm("{ .reg .u64 t; cvta.to.shared.u64 t, %1; cvt.u32.u64 %0, t; }" : "=r"(sb) : "l"(smem));
    int t = threadIdx.x, wid = t >> 5, lane = t & 31;
    int wm = wid & 1, wn = wid >> 1;
    char* cst = smem + SM_TILES;
    uint32_t stage_sa = sb + SM_TILES;

    int* stok = (int*)(smem + SM_TOK);
    float* sg = (float*)(smem + SM_G);
    if (t < 128) {
        int i = m0 + t;
        bool v = i < cnt;
        stok[t] = v ? g_tok[ex * NTOK + i] : -1;
        sg[t]   = v ? g_tokg[ex * NTOK + i] : 0.f;
    }
    __syncthreads();

    const float* B = eW + (size_t)ex * DMODEL * DOUT;

    float acc[4][4][4];
#pragma unroll
    for (int i = 0; i < 4; i++)
#pragma unroll
        for (int j = 0; j < 4; j++)
#pragma unroll
            for (int k = 0; k < 4; k++) acc[i][j][k] = 0.f;

    int k4 = t & 15, rbase = t >> 4;
    for (int kt = 0; kt < DMODEL / KT; kt++) {
        // gathered A tile
#pragma unroll
        for (int p = 0; p < 8; p++) {
            int r = p * 16 + rbase;
            int tok = stok[r];
            float4 v = (tok >= 0)
                ? *(const float4*)(g_x + (size_t)tok * DMODEL + kt * KT + k4 * 4)
                : make_float4(0.f, 0.f, 0.f, 0.f);
            split_store4(cst + TILE_A_HI, cst + TILE_A_LO, r * 128 + k4 * 8, v);
        }
        load_tile_transposed(cst + TILE_B_HI, cst + TILE_B_LO,
                             B + (size_t)(kt * KT) * DOUT + n0, DOUT, t);
        __syncthreads();
        compute_stage(stage_sa, wm, wn, lane, acc);
        __syncthreads();
    }

    const float* bias = eB + (size_t)ex * DOUT;
#pragma unroll
    for (int mt = 0; mt < 4; mt++)
#pragma unroll
        for (int nt = 0; nt < 4; nt++) {
            int r = wm * 64 + mt * 16 + (lane >> 2);
            int c = n0 + wn * 32 + nt * 8 + (lane & 3) * 2;
#pragma unroll
            for (int half = 0; half < 2; half++) {
                int rr = r + half * 8;
                int tok = stok[rr];
                if (tok >= 0) {
                    float g = sg[rr];
                    float* op = out + (size_t)tok * DOUT + c;
                    atomicAdd(op,     g * (acc[mt][nt][half * 2 + 0] + bias[c]));
                    atomicAdd(op + 1, g * (acc[mt][nt][half * 2 + 1] + bias[c + 1]));
                }
            }
        }
}

// ---------------------------------------------------------------------------
// Launch
// ---------------------------------------------------------------------------
extern "C" void kernel_launch(void* const* d_in, const int* in_sizes, int n_in,
                              void* d_out, int out_size) {
    const float* data     = (const float*)d_in[0];
    const float* W_q      = (const float*)d_in[1];
    const float* keys     = (const float*)d_in[2];
    const float* values   = (const float*)d_in[3];
    const float* gate_W   = (const float*)d_in[4];
    const float* gate_b   = (const float*)d_in[5];
    const float* expert_W = (const float*)d_in[6];
    const float* expert_b = (const float*)d_in[7];
    float* out = (float*)d_out;
    (void)in_sizes; (void)n_in;

    cudaFuncSetAttribute(mm_q_kernel, cudaFuncAttributeMaxDynamicSharedMemorySize, SMEM_TOTAL_GEMM);
    cudaFuncSetAttribute(mm_scores_kernel, cudaFuncAttributeMaxDynamicSharedMemorySize, SMEM_TOTAL_GEMM);
    cudaFuncSetAttribute(mm_expert_kernel, cudaFuncAttributeMaxDynamicSharedMemorySize, SMEM_TOTAL_GEMM);

    cudaMemsetAsync(out, 0, (size_t)out_size * sizeof(float));
    zero_cnt_kernel<<<1, 32>>>();

    mm_q_kernel<<<dim3(16, 16), 256, SMEM_TOTAL_GEMM>>>(data, W_q);
    mm_scores_kernel<<<dim3(2, 16, 8), 256, SMEM_TOTAL_GEMM>>>(keys);
    topk1_kernel<<<S1ROWS / 8, 256>>>();
    topk2_kernel<<<S2ROWS / 8, 256>>>();
    gather_kernel<<<NTOK, 256>>>(data, values);
    gate_route_kernel<<<NTOK, 128>>>(gate_W, gate_b);
    mm_expert_kernel<<<dim3(DOUT / BN, NTOK / BM, NEXP), 256, SMEM_TOTAL_GEMM>>>(expert_W, expert_b, out);
}

// round 5
// speedup vs baseline: 2.1257x; 1.1840x over previous
#include <cuda_runtime.h>
#include <cuda_bf16.h>
#include <math.h>
#include <float.h>
#include <stdint.h>

// ---------------------------------------------------------------------------
// Problem constants
// ---------------------------------------------------------------------------
#define NTOK 2048
#define DMODEL 1024
#define HEADS 4
#define HALF 256
#define NKEYS 256
#define KNN 16
#define NEXP 16
#define DOUT 1024
#define S1ROWS (NTOK * HEADS * 2)
#define S2ROWS (NTOK * HEADS)

// ---------------------------------------------------------------------------
// GEMM tiling: 128x128 CTA tile, K-chunk 64 bf16 (128B rows, SW128 swizzle),
// 2-stage cp.async double buffer. 8 warps 2(M)x4(N), warp tile 64x32.
// 3-term split GEMM: C = Ahi*Bhi + Alo*Bhi + Ahi*Blo (pre-split operands).
// ---------------------------------------------------------------------------
#define BM 128
#define BN 128
#define KT 64

#define SM_TOK   64
#define SM_G     576
#define SM_TILES 2048
#define TILE_A_HI 0
#define TILE_A_LO 16384
#define TILE_B_HI 32768
#define TILE_B_LO 49152
#define STAGE_BYTES 65536
#define SMEM_TOTAL_GEMM (SM_TILES + 2 * STAGE_BYTES)   // 133120 bytes

#define SW128(x) ((x) ^ (((x) >> 3) & 0x70))

// ---------------------------------------------------------------------------
// PTX wrappers (sm_80+ baseline)
// ---------------------------------------------------------------------------
static __device__ __forceinline__ void ldsm4(uint32_t* r, uint32_t sa) {
    asm volatile("ldmatrix.sync.aligned.m8n8.x4.shared.b16 {%0,%1,%2,%3}, [%4];"
                 : "=r"(r[0]), "=r"(r[1]), "=r"(r[2]), "=r"(r[3]) : "r"(sa));
}
static __device__ __forceinline__ void mma16816(float* c, const uint32_t* a,
                                                uint32_t b0, uint32_t b1) {
    asm volatile("mma.sync.aligned.m16n8k16.row.col.f32.bf16.bf16.f32 "
                 "{%0,%1,%2,%3}, {%4,%5,%6,%7}, {%8,%9}, {%0,%1,%2,%3};"
                 : "+f"(c[0]), "+f"(c[1]), "+f"(c[2]), "+f"(c[3])
                 : "r"(a[0]), "r"(a[1]), "r"(a[2]), "r"(a[3]), "r"(b0), "r"(b1));
}
static __device__ __forceinline__ void cpa16(uint32_t dst, const void* src) {
    asm volatile("cp.async.cg.shared.global [%0], [%1], 16;" :: "r"(dst), "l"(src));
}
#define CP_COMMIT() asm volatile("cp.async.commit_group;" ::: "memory")
#define CP_WAIT1()  asm volatile("cp.async.wait_group 1;" ::: "memory")
#define CP_WAIT0()  asm volatile("cp.async.wait_group 0;" ::: "memory")

// ordered-uint mapping for float max via REDUX
static __device__ __forceinline__ unsigned ordf(float f) {
    unsigned u = __float_as_uint(f);
    return (u >> 31) ? ~u : (u | 0x80000000u);
}
static __device__ __forceinline__ float deordf(unsigned u) {
    return __uint_as_float((u & 0x80000000u) ? (u ^ 0x80000000u) : ~u);
}

// ---------------------------------------------------------------------------
// Device scratch (pre-split bf16 hi/lo operands + pipeline intermediates)
// ---------------------------------------------------------------------------
__device__ __align__(256) __nv_bfloat16 g_data_hi[(size_t)NTOK * DMODEL];
__device__ __align__(256) __nv_bfloat16 g_data_lo[(size_t)NTOK * DMODEL];
__device__ __align__(256) __nv_bfloat16 g_wq_hi[(size_t)2048 * DMODEL];   // [N=2048][K=1024]
__device__ __align__(256) __nv_bfloat16 g_wq_lo[(size_t)2048 * DMODEL];
__device__ __align__(256) __nv_bfloat16 g_keys_hi[(size_t)8 * NKEYS * HALF];
__device__ __align__(256) __nv_bfloat16 g_keys_lo[(size_t)8 * NKEYS * HALF];
__device__ __align__(256) __nv_bfloat16 g_ew_hi[(size_t)NEXP * DOUT * DMODEL]; // [E][DOUT][D]
__device__ __align__(256) __nv_bfloat16 g_ew_lo[(size_t)NEXP * DOUT * DMODEL];
__device__ __align__(256) __nv_bfloat16 g_q_hi[(size_t)NTOK * 2048];
__device__ __align__(256) __nv_bfloat16 g_q_lo[(size_t)NTOK * 2048];
__device__ __align__(256) __nv_bfloat16 g_x_hi[(size_t)NTOK * DMODEL];
__device__ __align__(256) __nv_bfloat16 g_x_lo[(size_t)NTOK * DMODEL];
__device__ __align__(256) float g_scores[(size_t)NTOK * 2048];
__device__ __align__(256) float g_x[(size_t)NTOK * DMODEL];
__device__ float g_v1[(size_t)S1ROWS * KNN];
__device__ int   g_i1[(size_t)S1ROWS * KNN];
__device__ float g_w[(size_t)S2ROWS * KNN];
__device__ int   g_idx[(size_t)S2ROWS * KNN];
__device__ int   g_cnt[NEXP];
__device__ int   g_tok[NEXP * NTOK];
__device__ float g_tokg[NEXP * NTOK];

__global__ void zero_cnt_kernel() {
    if (threadIdx.x < NEXP) g_cnt[threadIdx.x] = 0;
}

// ---------------------------------------------------------------------------
// Pre-split helpers
// ---------------------------------------------------------------------------
static __device__ __forceinline__ uint2 pack_hi4(float4 v, float4* resid) {
    __nv_bfloat16 h0 = __float2bfloat16(v.x), h1 = __float2bfloat16(v.y),
                  h2 = __float2bfloat16(v.z), h3 = __float2bfloat16(v.w);
    resid->x = v.x - __bfloat162float(h0);
    resid->y = v.y - __bfloat162float(h1);
    resid->z = v.z - __bfloat162float(h2);
    resid->w = v.w - __bfloat162float(h3);
    uint2 r;
    r.x = (uint32_t)__bfloat16_as_ushort(h0) | ((uint32_t)__bfloat16_as_ushort(h1) << 16);
    r.y = (uint32_t)__bfloat16_as_ushort(h2) | ((uint32_t)__bfloat16_as_ushort(h3) << 16);
    return r;
}
static __device__ __forceinline__ uint2 pack_bf4(float4 v) {
    __nv_bfloat16 b0 = __float2bfloat16(v.x), b1 = __float2bfloat16(v.y),
                  b2 = __float2bfloat16(v.z), b3 = __float2bfloat16(v.w);
    uint2 r;
    r.x = (uint32_t)__bfloat16_as_ushort(b0) | ((uint32_t)__bfloat16_as_ushort(b1) << 16);
    r.y = (uint32_t)__bfloat16_as_ushort(b2) | ((uint32_t)__bfloat16_as_ushort(b3) << 16);
    return r;
}

static __device__ __forceinline__ void split_stream_body(const float* in,
                                                         __nv_bfloat16* hi,
                                                         __nv_bfloat16* lo, int n4) {
    int i = blockIdx.x * 256 + threadIdx.x;
    if (i >= n4) return;
    float4 v = ((const float4*)in)[i];
    float4 resid;
    uint2 hv = pack_hi4(v, &resid);
    uint2 lv = pack_bf4(resid);
    ((uint2*)hi)[i] = hv;
    ((uint2*)lo)[i] = lv;
}

__global__ __launch_bounds__(256) void split_data_kernel(const float* __restrict__ in) {
    split_stream_body(in, g_data_hi, g_data_lo, NTOK * DMODEL / 4);
}
__global__ __launch_bounds__(256) void split_keys_kernel(const float* __restrict__ in) {
    split_stream_body(in, g_keys_hi, g_keys_lo, 8 * NKEYS * HALF / 4);
}

// in: [K][N] fp32 (batch via grid.z) -> out: [N][K] bf16 hi/lo
static __device__ __forceinline__ void split_transpose_body(const float* in,
                                                            __nv_bfloat16* hi,
                                                            __nv_bfloat16* lo,
                                                            int K, int N) {
    __shared__ float tile[32][33];
    size_t bo = (size_t)blockIdx.z * K * N;
    const float* src = in + bo;
    __nv_bfloat16* dhi = hi + bo;
    __nv_bfloat16* dlo = lo + bo;
    int k0 = blockIdx.y * 32, n0 = blockIdx.x * 32;
    int tx = threadIdx.x & 31, ty = threadIdx.x >> 5;   // (32,8)
#pragma unroll
    for (int j = 0; j < 4; j++)
        tile[ty + j * 8][tx] = src[(size_t)(k0 + ty + j * 8) * N + n0 + tx];
    __syncthreads();
#pragma unroll
    for (int j = 0; j < 4; j++) {
        int n = n0 + ty + j * 8;
        float f = tile[tx][ty + j * 8];
        size_t o = (size_t)n * K + k0 + tx;
        __nv_bfloat16 h = __float2bfloat16(f);
        dhi[o] = h;
        dlo[o] = __float2bfloat16(f - __bfloat162float(h));
    }
}

__global__ __launch_bounds__(256) void split_wq_kernel(const float* __restrict__ in) {
    split_transpose_body(in, g_wq_hi, g_wq_lo, DMODEL, 2048);
}
__global__ __launch_bounds__(256) void split_ew_kernel(const float* __restrict__ in) {
    split_transpose_body(in, g_ew_hi, g_ew_lo, DMODEL, DOUT);
}

// ---------------------------------------------------------------------------
// Stage loader: cp.async 16B chunks into swizzled hi/lo tiles (A and B).
// ---------------------------------------------------------------------------
static __device__ __forceinline__ void stage_load(uint32_t stage_sa,
                                                  const __nv_bfloat16* Ahi, const __nv_bfloat16* Alo, int strideA,
                                                  const __nv_bfloat16* Bhi, const __nv_bfloat16* Blo, int strideB,
                                                  int t) {
    int c = (t & 7) * 16;
    int r0 = t >> 3;
#pragma unroll
    for (int p = 0; p < 4; p++) {
        int r = r0 + p * 32;
        uint32_t off = SW128(r * 128 + c);
        cpa16(stage_sa + TILE_A_HI + off, (const char*)Ahi + (size_t)r * strideA * 2 + c);
        cpa16(stage_sa + TILE_A_LO + off, (const char*)Alo + (size_t)r * strideA * 2 + c);
        cpa16(stage_sa + TILE_B_HI + off, (const char*)Bhi + (size_t)r * strideB * 2 + c);
        cpa16(stage_sa + TILE_B_LO + off, (const char*)Blo + (size_t)r * strideB * 2 + c);
    }
}

// ---------------------------------------------------------------------------
// Warp compute over one 64-k stage (3-pass split).
// ---------------------------------------------------------------------------
static __device__ __forceinline__ void compute_stage(uint32_t stage_sa, int wm, int wn,
                                                     int lane, float acc[4][4][4]) {
    uint32_t aHI = stage_sa + TILE_A_HI, aLO = stage_sa + TILE_A_LO;
    uint32_t bHI = stage_sa + TILE_B_HI, bLO = stage_sa + TILE_B_LO;
    int lrow = lane & 15;
    int lcol = (lane >> 4) * 16;

#pragma unroll
    for (int ks = 0; ks < 4; ks++) {
        int kb = ks * 32;
        uint32_t bh[2][4], bl[2][4];
#pragma unroll
        for (int np = 0; np < 2; np++) {
            int boff = SW128((wn * 32 + np * 16 + lrow) * 128 + kb + lcol);
            ldsm4(bh[np], bHI + boff);
            ldsm4(bl[np], bLO + boff);
        }
#pragma unroll
        for (int mt = 0; mt < 4; mt++) {
            uint32_t ah[4], al[4];
            int aoff = SW128((wm * 64 + mt * 16 + lrow) * 128 + kb + lcol);
            ldsm4(ah, aHI + aoff);
            ldsm4(al, aLO + aoff);
#pragma unroll
            for (int nt = 0; nt < 4; nt++) {
                int np = nt >> 1, h = nt & 1;
                mma16816(acc[mt][nt], ah, bh[np][h], bh[np][h + 2]);
                mma16816(acc[mt][nt], al, bh[np][h], bh[np][h + 2]);
                mma16816(acc[mt][nt], ah, bl[np][h], bl[np][h + 2]);
            }
        }
    }
}

#define ACC_ZERO(acc) \
    _Pragma("unroll") for (int i = 0; i < 4; i++) \
    _Pragma("unroll") for (int j = 0; j < 4; j++) \
    _Pragma("unroll") for (int k = 0; k < 4; k++) acc[i][j][k] = 0.f

// ---------------------------------------------------------------------------
// Kernel: q = data @ W_q, writes q directly as bf16 hi/lo. grid(16,16).
// ---------------------------------------------------------------------------
__global__ __launch_bounds__(256, 1) void mm_q_kernel() {
    extern __shared__ char smem[];
    uint32_t sb;
    asm("{ .reg .u64 t; cvta.to.shared.u64 t, %1; cvt.u32.u64 %0, t; }" : "=r"(sb) : "l"(smem));
    int t = threadIdx.x, wid = t >> 5, lane = t & 31;
    int wm = wid & 1, wn = wid >> 1;
    int m0 = blockIdx.y * BM, n0 = blockIdx.x * BN;

    const __nv_bfloat16* Ahi = g_data_hi + (size_t)m0 * DMODEL;
    const __nv_bfloat16* Alo = g_data_lo + (size_t)m0 * DMODEL;
    const __nv_bfloat16* Bhi = g_wq_hi + (size_t)n0 * DMODEL;
    const __nv_bfloat16* Blo = g_wq_lo + (size_t)n0 * DMODEL;

    float acc[4][4][4];
    ACC_ZERO(acc);

    const int NKT = DMODEL / KT;  // 16
    stage_load(sb + SM_TILES, Ahi, Alo, DMODEL, Bhi, Blo, DMODEL, t);
    CP_COMMIT();
    for (int kt = 0; kt < NKT; kt++) {
        if (kt + 1 < NKT) {
            int koff = (kt + 1) * KT;
            stage_load(sb + SM_TILES + ((kt + 1) & 1) * STAGE_BYTES,
                       Ahi + koff, Alo + koff, DMODEL, Bhi + koff, Blo + koff, DMODEL, t);
            CP_COMMIT();
            CP_WAIT1();
        } else {
            CP_WAIT0();
        }
        __syncthreads();
        compute_stage(sb + SM_TILES + (kt & 1) * STAGE_BYTES, wm, wn, lane, acc);
        __syncthreads();
    }

#pragma unroll
    for (int mt = 0; mt < 4; mt++)
#pragma unroll
        for (int nt = 0; nt < 4; nt++) {
            int r = m0 + wm * 64 + mt * 16 + (lane >> 2);
            int c = n0 + wn * 32 + nt * 8 + (lane & 3) * 2;
#pragma unroll
            for (int half = 0; half < 2; half++) {
                float a = acc[mt][nt][half * 2 + 0];
                float b = acc[mt][nt][half * 2 + 1];
                size_t o = (size_t)(r + half * 8) * 2048 + c;
                __nv_bfloat16 ha = __float2bfloat16(a), hb = __float2bfloat16(b);
                __nv_bfloat16 la = __float2bfloat16(a - __bfloat162float(ha));
                __nv_bfloat16 lb = __float2bfloat16(b - __bfloat162float(hb));
                *(uint32_t*)(g_q_hi + o) =
                    (uint32_t)__bfloat16_as_ushort(ha) | ((uint32_t)__bfloat16_as_ushort(hb) << 16);
                *(uint32_t*)(g_q_lo + o) =
                    (uint32_t)__bfloat16_as_ushort(la) | ((uint32_t)__bfloat16_as_ushort(lb) << 16);
            }
        }
}

// ---------------------------------------------------------------------------
// Kernel: scores. grid(2,16,8): x=key tile, y=token tile, z=hc.
// ---------------------------------------------------------------------------
__global__ __launch_bounds__(256, 1) void mm_scores_kernel() {
    extern __shared__ char smem[];
    uint32_t sb;
    asm("{ .reg .u64 t; cvta.to.shared.u64 t, %1; cvt.u32.u64 %0, t; }" : "=r"(sb) : "l"(smem));
    int t = threadIdx.x, wid = t >> 5, lane = t & 31;
    int wm = wid & 1, wn = wid >> 1;
    int hc = blockIdx.z;
    int m0 = blockIdx.y * BM, n0 = blockIdx.x * BN;

    const __nv_bfloat16* Ahi = g_q_hi + (size_t)m0 * 2048 + hc * HALF;
    const __nv_bfloat16* Alo = g_q_lo + (size_t)m0 * 2048 + hc * HALF;
    const __nv_bfloat16* Bhi = g_keys_hi + (size_t)hc * NKEYS * HALF + (size_t)n0 * HALF;
    const __nv_bfloat16* Blo = g_keys_lo + (size_t)hc * NKEYS * HALF + (size_t)n0 * HALF;

    float acc[4][4][4];
    ACC_ZERO(acc);

    const int NKT = HALF / KT;  // 4
    stage_load(sb + SM_TILES, Ahi, Alo, 2048, Bhi, Blo, HALF, t);
    CP_COMMIT();
    for (int kt = 0; kt < NKT; kt++) {
        if (kt + 1 < NKT) {
            int koff = (kt + 1) * KT;
            stage_load(sb + SM_TILES + ((kt + 1) & 1) * STAGE_BYTES,
                       Ahi + koff, Alo + koff, 2048, Bhi + koff, Blo + koff, HALF, t);
            CP_COMMIT();
            CP_WAIT1();
        } else {
            CP_WAIT0();
        }
        __syncthreads();
        compute_stage(sb + SM_TILES + (kt & 1) * STAGE_BYTES, wm, wn, lane, acc);
        __syncthreads();
    }

#pragma unroll
    for (int mt = 0; mt < 4; mt++)
#pragma unroll
        for (int nt = 0; nt < 4; nt++) {
            int r = m0 + wm * 64 + mt * 16 + (lane >> 2);
            int c = hc * NKEYS + n0 + wn * 32 + nt * 8 + (lane & 3) * 2;
            *(float2*)(g_scores + (size_t)r * 2048 + c) =
                make_float2(acc[mt][nt][0], acc[mt][nt][1]);
            *(float2*)(g_scores + (size_t)(r + 8) * 2048 + c) =
                make_float2(acc[mt][nt][2], acc[mt][nt][3]);
        }
}

// ---------------------------------------------------------------------------
// Kernel: stage-1 top-16 via REDUX max. One warp per row.
// ---------------------------------------------------------------------------
__global__ __launch_bounds__(256) void topk1_kernel() {
    int row  = (blockIdx.x * blockDim.x + threadIdx.x) >> 5;
    int lane = threadIdx.x & 31;
    const float* src = g_scores + (size_t)row * NKEYS;

    unsigned lu[8];
#pragma unroll
    for (int r = 0; r < 8; r++) lu[r] = ordf(src[r * 32 + lane]);
    unsigned lmax = lu[0];
#pragma unroll
    for (int r = 1; r < 8; r++) lmax = max(lmax, lu[r]);

    float* vo = g_v1 + (size_t)row * KNN;
    int*   io = g_i1 + (size_t)row * KNN;

    for (int sel = 0; sel < KNN; sel++) {
        unsigned w = __reduce_max_sync(0xffffffffu, lmax);
        unsigned msk = __ballot_sync(0xffffffffu, lmax == w);
        int wl = __ffs(msk) - 1;
        if (lane == 0) vo[sel] = deordf(w);
        if (lane == wl) {
            int rs = 0;
#pragma unroll
            for (int r = 7; r >= 0; r--) if (lu[r] == w) rs = r;
            io[sel] = rs * 32 + lane;
            lu[rs] = 0;
            lmax = lu[0];
#pragma unroll
            for (int r = 1; r < 8; r++) lmax = max(lmax, lu[r]);
        }
    }
}

// ---------------------------------------------------------------------------
// Kernel: stage-2 cartesian top-16 + softmax via REDUX. One warp per (n,h).
// ---------------------------------------------------------------------------
__global__ __launch_bounds__(256) void topk2_kernel() {
    int row  = (blockIdx.x * blockDim.x + threadIdx.x) >> 5;
    int lane = threadIdx.x & 31;
    int wp   = threadIdx.x >> 5;

    __shared__ float sv1[8][16], sv2[8][16];
    __shared__ int   si1[8][16], si2[8][16];
    __shared__ float selv[8][16];
    __shared__ int   seli[8][16];

    int r1 = row * 2, r2 = row * 2 + 1;
    if (lane < 16) {
        sv1[wp][lane] = g_v1[(size_t)r1 * KNN + lane];
        si1[wp][lane] = g_i1[(size_t)r1 * KNN + lane];
    } else {
        sv2[wp][lane - 16] = g_v1[(size_t)r2 * KNN + (lane - 16)];
        si2[wp][lane - 16] = g_i1[(size_t)r2 * KNN + (lane - 16)];
    }
    __syncwarp();

    unsigned lu[8];
#pragma unroll
    for (int r = 0; r < 8; r++) {
        int c = r * 32 + lane;
        lu[r] = ordf(sv1[wp][c >> 4] + sv2[wp][c & 15]);
    }
    unsigned lmax = lu[0];
#pragma unroll
    for (int r = 1; r < 8; r++) lmax = max(lmax, lu[r]);

    for (int sel = 0; sel < KNN; sel++) {
        unsigned w = __reduce_max_sync(0xffffffffu, lmax);
        unsigned msk = __ballot_sync(0xffffffffu, lmax == w);
        int wl = __ffs(msk) - 1;
        if (lane == 0) selv[wp][sel] = deordf(w);
        if (lane == wl) {
            int rs = 0;
#pragma unroll
            for (int r = 7; r >= 0; r--) if (lu[r] == w) rs = r;
            int cand = rs * 32 + lane;
            seli[wp][sel] = si1[wp][cand >> 4] * NKEYS + si2[wp][cand & 15];
            lu[rs] = 0;
            lmax = lu[0];
#pragma unroll
            for (int r = 1; r < 8; r++) lmax = max(lmax, lu[r]);
        }
    }
    __syncwarp();

    float mx = selv[wp][0];
    float e = (lane < 16) ? expf(selv[wp][lane] - mx) : 0.f;
    float s = e;
#pragma unroll
    for (int off = 16; off; off >>= 1) s += __shfl_xor_sync(0xffffffffu, s, off);
    if (lane < 16) {
        g_w[(size_t)row * KNN + lane]   = e / s;
        g_idx[(size_t)row * KNN + lane] = seli[wp][lane];
    }
}

// ---------------------------------------------------------------------------
// Kernel: value gather + residual -> g_x fp32 + hi/lo bf16. One block/token.
// ---------------------------------------------------------------------------
__global__ __launch_bounds__(256) void gather_kernel(const float* __restrict__ data,
                                                     const float* __restrict__ values) {
    int n = blockIdx.x;
    int t = threadIdx.x;
    __shared__ float sw[HEADS * KNN];
    __shared__ int   sidx[HEADS * KNN];
    if (t < HEADS * KNN) {
        sw[t]   = g_w[(size_t)n * HEADS * KNN + t];
        sidx[t] = g_idx[(size_t)n * HEADS * KNN + t];
    }
    __syncthreads();

    float4 acc = *(const float4*)(data + (size_t)n * DMODEL + t * 4);
#pragma unroll 4
    for (int j = 0; j < HEADS * KNN; j++) {
        const float4 v = *(const float4*)(values + (size_t)sidx[j] * DMODEL + t * 4);
        float wj = sw[j];
        acc.x += wj * v.x; acc.y += wj * v.y;
        acc.z += wj * v.z; acc.w += wj * v.w;
    }
    size_t o = (size_t)n * DMODEL + t * 4;
    *(float4*)(g_x + o) = acc;
    float4 resid;
    uint2 hv = pack_hi4(acc, &resid);
    uint2 lv = pack_bf4(resid);
    *(uint2*)(g_x_hi + o) = hv;
    *(uint2*)(g_x_lo + o) = lv;
}

// ---------------------------------------------------------------------------
// Kernel: gating + top-2 routing. One block (128 thr) per token.
// ---------------------------------------------------------------------------
__global__ __launch_bounds__(128) void gate_route_kernel(const float* __restrict__ gW,
                                                         const float* __restrict__ gb) {
    int n = blockIdx.x;
    int t = threadIdx.x;
    int e = t & 15, seg = t >> 4;

    const float* xr = g_x + (size_t)n * DMODEL;
    float p = 0.f;
    int dbeg = seg * 128;
    for (int d = dbeg; d < dbeg + 128; d++) p += xr[d] * gW[d * NEXP + e];

    __shared__ float sacc[128];
    __shared__ float lg[NEXP];
    sacc[t] = p;
    __syncthreads();
    if (t < NEXP) {
        float s = 0.f;
        for (int sgi = 0; sgi < 8; sgi++) s += sacc[sgi * 16 + t];
        lg[t] = s + gb[t];
    }
    __syncthreads();
    if (t == 0) {
        int b0 = 0; float v0 = lg[0];
        for (int i = 1; i < NEXP; i++) if (lg[i] > v0) { v0 = lg[i]; b0 = i; }
        int b1 = -1; float v1 = -FLT_MAX;
        for (int i = 0; i < NEXP; i++) {
            if (i == b0) continue;
            if (lg[i] > v1) { v1 = lg[i]; b1 = i; }
        }
        float gate0 = 1.f / (1.f + expf(v1 - v0));
        float gate1 = 1.f - gate0;
        int p0 = atomicAdd(&g_cnt[b0], 1);
        g_tok[b0 * NTOK + p0] = n;  g_tokg[b0 * NTOK + p0] = gate0;
        int p1 = atomicAdd(&g_cnt[b1], 1);
        g_tok[b1 * NTOK + p1] = n;  g_tokg[b1 * NTOK + p1] = gate1;
    }
}

// ---------------------------------------------------------------------------
// Kernel: grouped expert GEMM (pipelined). grid(8, 16, NEXP), early exit.
// ---------------------------------------------------------------------------
static __device__ __forceinline__ void stage_load_expert(uint32_t stage_sa, const int* stok,
                                                         int koff,
                                                         const __nv_bfloat16* Bhi,
                                                         const __nv_bfloat16* Blo, int t) {
    int c = (t & 7) * 16;
    int r0 = t >> 3;
#pragma unroll
    for (int p = 0; p < 4; p++) {
        int r = r0 + p * 32;
        uint32_t off = SW128(r * 128 + c);
        int tok = stok[r];
        int base = tok >= 0 ? tok : 0;
        size_t ao = ((size_t)base * DMODEL + koff) * 2 + c;
        cpa16(stage_sa + TILE_A_HI + off, (const char*)g_x_hi + ao);
        cpa16(stage_sa + TILE_A_LO + off, (const char*)g_x_lo + ao);
        cpa16(stage_sa + TILE_B_HI + off, (const char*)Bhi + (size_t)r * DMODEL * 2 + c);
        cpa16(stage_sa + TILE_B_LO + off, (const char*)Blo + (size_t)r * DMODEL * 2 + c);
    }
}

__global__ __launch_bounds__(256, 1) void mm_expert_kernel(const float* __restrict__ eB,
                                                           float* __restrict__ out) {
    int ex  = blockIdx.z;
    int cnt = g_cnt[ex];
    int m0  = blockIdx.y * BM;
    if (m0 >= cnt) return;
    int n0 = blockIdx.x * BN;

    extern __shared__ char smem[];
    uint32_t sb;
    asm("{ .reg .u64 t; cvta.to.shared.u64 t, %1; cvt.u32.u64 %0, t; }" : "=r"(sb) : "l"(smem));
    int t = threadIdx.x, wid = t >> 5, lane = t & 31;
    int wm = wid & 1, wn = wid >> 1;

    int* stok = (int*)(smem + SM_TOK);
    float* sg = (float*)(smem + SM_G);
    if (t < 128) {
        int i = m0 + t;
        bool v = i < cnt;
        stok[t] = v ? g_tok[ex * NTOK + i] : -1;
        sg[t]   = v ? g_tokg[ex * NTOK + i] : 0.f;
    }
    __syncthreads();

    const __nv_bfloat16* Bhi = g_ew_hi + (size_t)ex * DOUT * DMODEL + (size_t)n0 * DMODEL;
    const __nv_bfloat16* Blo = g_ew_lo + (size_t)ex * DOUT * DMODEL + (size_t)n0 * DMODEL;

    float acc[4][4][4];
    ACC_ZERO(acc);

    const int NKT = DMODEL / KT;  // 16
    stage_load_expert(sb + SM_TILES, stok, 0, Bhi, Blo, t);
    CP_COMMIT();
    for (int kt = 0; kt < NKT; kt++) {
        if (kt + 1 < NKT) {
            int koff = (kt + 1) * KT;
            stage_load_expert(sb + SM_TILES + ((kt + 1) & 1) * STAGE_BYTES,
                              stok, koff, Bhi + koff, Blo + koff, t);
            CP_COMMIT();
            CP_WAIT1();
        } else {
            CP_WAIT0();
        }
        __syncthreads();
        compute_stage(sb + SM_TILES + (kt & 1) * STAGE_BYTES, wm, wn, lane, acc);
        __syncthreads();
    }

    const float* bias = eB + (size_t)ex * DOUT;
#pragma unroll
    for (int mt = 0; mt < 4; mt++)
#pragma unroll
        for (int nt = 0; nt < 4; nt++) {
            int r = wm * 64 + mt * 16 + (lane >> 2);
            int c = n0 + wn * 32 + nt * 8 + (lane & 3) * 2;
#pragma unroll
            for (int half = 0; half < 2; half++) {
                int rr = r + half * 8;
                int tok = stok[rr];
                if (tok >= 0) {
                    float g = sg[rr];
                    float* op = out + (size_t)tok * DOUT + c;
                    atomicAdd(op,     g * (acc[mt][nt][half * 2 + 0] + bias[c]));
                    atomicAdd(op + 1, g * (acc[mt][nt][half * 2 + 1] + bias[c + 1]));
                }
            }
        }
}

// ---------------------------------------------------------------------------
// Launch
// ---------------------------------------------------------------------------
extern "C" void kernel_launch(void* const* d_in, const int* in_sizes, int n_in,
                              void* d_out, int out_size) {
    const float* data     = (const float*)d_in[0];
    const float* W_q      = (const float*)d_in[1];
    const float* keys     = (const float*)d_in[2];
    const float* values   = (const float*)d_in[3];
    const float* gate_W   = (const float*)d_in[4];
    const float* gate_b   = (const float*)d_in[5];
    const float* expert_W = (const float*)d_in[6];
    const float* expert_b = (const float*)d_in[7];
    float* out = (float*)d_out;
    (void)in_sizes; (void)n_in;

    cudaFuncSetAttribute(mm_q_kernel, cudaFuncAttributeMaxDynamicSharedMemorySize, SMEM_TOTAL_GEMM);
    cudaFuncSetAttribute(mm_scores_kernel, cudaFuncAttributeMaxDynamicSharedMemorySize, SMEM_TOTAL_GEMM);
    cudaFuncSetAttribute(mm_expert_kernel, cudaFuncAttributeMaxDynamicSharedMemorySize, SMEM_TOTAL_GEMM);

    cudaMemsetAsync(out, 0, (size_t)out_size * sizeof(float));
    zero_cnt_kernel<<<1, 32>>>();

    // pre-split operands (writes go straight to __device__ symbols)
    split_data_kernel<<<(NTOK * DMODEL / 4 + 255) / 256, 256>>>(data);
    split_keys_kernel<<<(8 * NKEYS * HALF / 4 + 255) / 256, 256>>>(keys);
    split_wq_kernel<<<dim3(2048 / 32, DMODEL / 32, 1), 256>>>(W_q);

    // mainline
    mm_q_kernel<<<dim3(16, 16), 256, SMEM_TOTAL_GEMM>>>();

    split_ew_kernel<<<dim3(DOUT / 32, DMODEL / 32, NEXP), 256>>>(expert_W);

    mm_scores_kernel<<<dim3(2, 16, 8), 256, SMEM_TOTAL_GEMM>>>();
    topk1_kernel<<<S1ROWS / 8, 256>>>();
    topk2_kernel<<<S2ROWS / 8, 256>>>();
    gather_kernel<<<NTOK, 256>>>(data, values);
    gate_route_kernel<<<NTOK, 128>>>(gate_W, gate_b);
    mm_expert_kernel<<<dim3(DOUT / BN, NTOK / BM, NEXP), 256, SMEM_TOTAL_GEMM>>>(expert_b, out);
}